// round 6
// baseline (speedup 1.0000x reference)
#include <cuda_runtime.h>
#include <cstdint>

// Decoder_2430951489916 — v6: single-wave grid, minimal-barrier, short tail.
//   B=4, N=512, M=512, ZD=128, YD=2, XD=1
// out[b,m,y] = b_y + sum_n sum_c W[y,c]*z[b,n,c]*exp(-0.5*((x_m-t_n)*exp(-sigma_c))^2)
// Fast path (uniform sigma, true for bench):
//   out[b,m,y] = b_y + sum_n exp(coef*(x_m-t_n)^2) * zw[b,n,y],  zw = z @ W^T.
//
// Model finding (R5): compute is ~0.3us; time = launch floor + structural
// overhead. So: 128 blocks (single wave on 148 SMs), 512 threads; each block
// owns a 16-row n-chunk of one batch (z read exactly once, coalesced, warp w
// reduces row w); each thread owns m=tid and computes its 16 exp terms from
// broadcast-__ldg t while z is in flight. ONE __syncthreads. Combine across
// the 32 chunk-blocks per batch via relaxed red.add into zero-init scratch +
// acq_rel per-point counter; 32nd arriver writes out = bias + acc and resets
// scratch (graph-replay safe).

#define BB 4
#define NN 512
#define MM 512
#define ZDIM 128
#define YDIM 2
#define CHUNK 16
#define NCHUNKS (NN / CHUNK)        // 32
#define NTHREADS 512
#define GRID (BB * NCHUNKS)         // 128  (single wave)
#define NCONTRIB NCHUNKS            // 32 adds per output point

__device__ float    g_acc[BB * MM * YDIM];   // zero-init (.bss), self-resetting
__device__ unsigned g_cnt[BB * MM];          // zero-init (.bss), self-resetting

__device__ __forceinline__ void red_add_f32(float* p, float v) {
    asm volatile("red.relaxed.gpu.global.add.f32 [%0], %1;" :: "l"(p), "f"(v) : "memory");
}
__device__ __forceinline__ unsigned atom_inc_acqrel(unsigned* p) {
    unsigned old;
    asm volatile("atom.acq_rel.gpu.global.add.u32 %0, [%1], 1;" : "=r"(old) : "l"(p) : "memory");
    return old;
}
__device__ __forceinline__ float ld_relaxed_f32(const float* p) {
    float v;
    asm volatile("ld.relaxed.gpu.global.f32 %0, [%1];" : "=f"(v) : "l"(p) : "memory");
    return v;
}
__device__ __forceinline__ void st_relaxed_f32(float* p, float v) {
    asm volatile("st.relaxed.gpu.global.f32 [%0], %1;" :: "l"(p), "f"(v) : "memory");
}
__device__ __forceinline__ void st_relaxed_u32(unsigned* p, unsigned v) {
    asm volatile("st.relaxed.gpu.global.u32 [%0], %1;" :: "l"(p), "r"(v) : "memory");
}

__global__ __launch_bounds__(NTHREADS) void decoder_v6(
    const float* __restrict__ t,
    const float* __restrict__ z,
    const float* __restrict__ x,
    const float* __restrict__ sigma,
    const float* __restrict__ W,
    const float* __restrict__ bias,
    float* __restrict__ out) {
    __shared__ float zw0_s[CHUNK];
    __shared__ float zw1_s[CHUNK];
    __shared__ int   nonuniform;

    const int tid   = threadIdx.x;
    const int wid   = tid >> 5;          // 0..15 -> owns z row n0+wid
    const int lane  = tid & 31;
    const int b     = blockIdx.x / NCHUNKS;
    const int chunk = blockIdx.x % NCHUNKS;
    const int n0    = chunk * CHUNK;

    if (tid == 0) nonuniform = 0;

    // --- issue all long-latency loads up front ---
    const int    m   = tid;                               // one m-point per thread
    const float  xm  = __ldg(x + b * MM + m);             // XD == 1
    const float4 zv  = __ldg((const float4*)(z + (size_t)(b * NN + n0 + wid) * ZDIM) + lane);
    const float4 w0v = __ldg((const float4*)W + lane);
    const float4 w1v = __ldg((const float4*)W + 32 + lane);
    const float  b0  = __ldg(bias + 0);
    const float  b1  = __ldg(bias + 1);

    // sigma uniformity (flag read after the single barrier below)
    const float s0 = __ldg(sigma);
    if (tid < ZDIM && __ldg(sigma + tid) != s0) atomicOr(&nonuniform, 1);
    const float coef = -0.5f * __expf(-2.0f * s0);

    // --- exp terms from broadcast t loads (overlaps z latency; no smem, no bar) ---
    const float* tg = t + b * NN + n0;
    float e[CHUNK];
#pragma unroll
    for (int n = 0; n < CHUNK; ++n) {
        const float d = xm - __ldg(tg + n);               // warp-uniform broadcast
        e[n] = __expf(coef * d * d);
    }

    // --- zw for this chunk: warp w reduces its row ---
    {
        float a0 = zv.x * w0v.x;  a0 = fmaf(zv.y, w0v.y, a0);
        a0 = fmaf(zv.z, w0v.z, a0); a0 = fmaf(zv.w, w0v.w, a0);
        float a1 = zv.x * w1v.x;  a1 = fmaf(zv.y, w1v.y, a1);
        a1 = fmaf(zv.z, w1v.z, a1); a1 = fmaf(zv.w, w1v.w, a1);
#pragma unroll
        for (int o = 16; o; o >>= 1) {
            a0 += __shfl_xor_sync(0xFFFFFFFFu, a0, o);
            a1 += __shfl_xor_sync(0xFFFFFFFFu, a1, o);
        }
        if (lane == 0) { zw0_s[wid] = a0; zw1_s[wid] = a1; }
    }
    __syncthreads();                                      // the only barrier

    float s_0, s_1;
    if (!nonuniform) {
        // two independent accumulation chains per output to halve serial depth
        float p0 = e[0] * zw0_s[0], q0 = e[1] * zw0_s[1];
        float p1 = e[0] * zw1_s[0], q1 = e[1] * zw1_s[1];
#pragma unroll
        for (int n = 2; n < CHUNK; n += 2) {
            p0 = fmaf(e[n],     zw0_s[n],     p0);
            q0 = fmaf(e[n + 1], zw0_s[n + 1], q0);
            p1 = fmaf(e[n],     zw1_s[n],     p1);
            q1 = fmaf(e[n + 1], zw1_s[n + 1], q1);
        }
        s_0 = p0 + q0;
        s_1 = p1 + q1;
    } else {
        // general path: per-channel length scales (correct for any sigma)
        s_0 = 0.f; s_1 = 0.f;
        for (int n = 0; n < CHUNK; ++n) {
            const float d  = xm - __ldg(tg + n);
            const float d2 = d * d;
            const float* zr = z + (size_t)(b * NN + n0 + n) * ZDIM;
            for (int c = 0; c < ZDIM; ++c) {
                const float inv = __expf(-__ldg(sigma + c));
                const float qq  = -0.5f * inv * inv;
                const float ev  = __ldg(zr + c) * __expf(qq * d2);
                s_0 = fmaf(ev, __ldg(W + c),        s_0);
                s_1 = fmaf(ev, __ldg(W + ZDIM + c), s_1);
            }
        }
    }

    // --- combine across the 32 chunk-blocks of this batch ---
    const int pt  = b * MM + m;                           // 0..2047
    float*    acc = g_acc + 2 * pt;
    red_add_f32(acc + 0, s_0);
    red_add_f32(acc + 1, s_1);
    const unsigned old = atom_inc_acqrel(&g_cnt[pt]);
    if (old == NCONTRIB - 1) {
        const float a0 = ld_relaxed_f32(acc + 0);
        const float a1 = ld_relaxed_f32(acc + 1);
        out[2 * pt + 0] = a0 + b0;
        out[2 * pt + 1] = a1 + b1;
        st_relaxed_f32(acc + 0, 0.0f);                    // reset for next replay
        st_relaxed_f32(acc + 1, 0.0f);
        st_relaxed_u32(&g_cnt[pt], 0u);
    }
}

// ---------------------------------------------------------------------------
extern "C" void kernel_launch(void* const* d_in, const int* in_sizes, int n_in,
                              void* d_out, int out_size) {
    const float* t     = (const float*)d_in[0];
    const float* z     = (const float*)d_in[1];
    const float* x     = (const float*)d_in[2];
    const float* sigma = (const float*)d_in[3];
    const float* W     = (const float*)d_in[4];
    const float* bias  = (const float*)d_in[5];
    float* out = (float*)d_out;

    decoder_v6<<<GRID, NTHREADS>>>(t, z, x, sigma, W, bias, out);
}

// round 7
// speedup vs baseline: 1.0295x; 1.0295x over previous
#include <cuda_runtime.h>
#include <cstdint>

// Decoder_2430951489916 — v7: R5 structure (best measured) + merged-barrier
// uniformity vote + vectorized v2.f32 reduction tail.
//   B=4, N=512, M=512, ZD=128, YD=2, XD=1
// out[b,m,y] = b_y + sum_n sum_c W[y,c]*z[b,n,c]*exp(-0.5*((x_m-t_n)*exp(-sigma_c))^2)
// Fast path (uniform sigma, true for bench):
//   out[b,m,y] = b_y + sum_n exp(coef*(x_m-t_n)^2) * zw[b,n,y],  zw = z @ W^T.
//
// 256 blocks = 4 batches x 64 chunks of 8 n-rows; 512 threads; warps 0-7 each
// reduce one z-row (z read exactly once, coalesced float4); every thread owns
// m = tid and computes its 8 exp terms from broadcast __ldg(t) while z is in
// flight. ONE barrier (__syncthreads_or, doubling as the sigma-uniformity
// vote). Combine across the 64 chunk-blocks per batch with a single
// red.add.v2.f32 per thread into zero-init scratch + per-point acq_rel
// counter; 64th arriver writes out = bias + acc and resets (replay-safe).

#define BB 4
#define NN 512
#define MM 512
#define ZDIM 128
#define YDIM 2
#define CHUNK 8
#define NCHUNKS (NN / CHUNK)        // 64
#define NTHREADS 512
#define GRID (BB * NCHUNKS)         // 256
#define NCONTRIB NCHUNKS            // 64 adds per output point

__device__ float    g_acc[BB * MM * YDIM];   // zero-init (.bss), self-resetting
__device__ unsigned g_cnt[BB * MM];          // zero-init (.bss), self-resetting

__device__ __forceinline__ void red_add_v2(float* p, float a, float b) {
    asm volatile("red.relaxed.gpu.global.add.v2.f32 [%0], {%1,%2};"
                 :: "l"(p), "f"(a), "f"(b) : "memory");
}
__device__ __forceinline__ unsigned atom_inc_acqrel(unsigned* p) {
    unsigned old;
    asm volatile("atom.acq_rel.gpu.global.add.u32 %0, [%1], 1;" : "=r"(old) : "l"(p) : "memory");
    return old;
}
__device__ __forceinline__ void ld_relaxed_v2(const float* p, float& a, float& b) {
    asm volatile("ld.relaxed.gpu.global.v2.f32 {%0,%1}, [%2];"
                 : "=f"(a), "=f"(b) : "l"(p) : "memory");
}
__device__ __forceinline__ void st_relaxed_v2(float* p, float a, float b) {
    asm volatile("st.relaxed.gpu.global.v2.f32 [%0], {%1,%2};"
                 :: "l"(p), "f"(a), "f"(b) : "memory");
}
__device__ __forceinline__ void st_relaxed_u32(unsigned* p, unsigned v) {
    asm volatile("st.relaxed.gpu.global.u32 [%0], %1;" :: "l"(p), "r"(v) : "memory");
}

__global__ __launch_bounds__(NTHREADS) void decoder_v7(
    const float* __restrict__ t,
    const float* __restrict__ z,
    const float* __restrict__ x,
    const float* __restrict__ sigma,
    const float* __restrict__ W,
    const float* __restrict__ bias,
    float* __restrict__ out) {
    __shared__ float zw0_s[CHUNK];
    __shared__ float zw1_s[CHUNK];

    const int tid   = threadIdx.x;
    const int wid   = tid >> 5;          // warps 0..7 own a z row
    const int lane  = tid & 31;
    const int b     = blockIdx.x / NCHUNKS;
    const int chunk = blockIdx.x % NCHUNKS;
    const int n0    = chunk * CHUNK;

    // --- issue all long-latency loads up front (single DRAM round) ---
    const int    m   = tid;                               // one m-point per thread
    const float  xm  = __ldg(x + b * MM + m);             // XD == 1
    const float  b0  = __ldg(bias + 0);
    const float  b1  = __ldg(bias + 1);
    const float  s0  = __ldg(sigma);

    float4 zv, w0v, w1v;
    if (wid < CHUNK) {
        zv  = __ldg((const float4*)(z + (size_t)(b * NN + n0 + wid) * ZDIM) + lane);
        w0v = __ldg((const float4*)W + lane);
        w1v = __ldg((const float4*)W + 32 + lane);
    }

    const float coef = -0.5f * __expf(-2.0f * s0);

    // --- exp terms from broadcast t loads (overlaps z latency) ---
    const float* tg = t + b * NN + n0;
    float e[CHUNK];
#pragma unroll
    for (int n = 0; n < CHUNK; ++n) {
        const float d = xm - __ldg(tg + n);               // warp-uniform broadcast
        e[n] = __expf(coef * d * d);
    }

    // --- zw for this chunk: warp w reduces its row ---
    if (wid < CHUNK) {
        float a0 = zv.x * w0v.x;  a0 = fmaf(zv.y, w0v.y, a0);
        a0 = fmaf(zv.z, w0v.z, a0); a0 = fmaf(zv.w, w0v.w, a0);
        float a1 = zv.x * w1v.x;  a1 = fmaf(zv.y, w1v.y, a1);
        a1 = fmaf(zv.z, w1v.z, a1); a1 = fmaf(zv.w, w1v.w, a1);
#pragma unroll
        for (int o = 16; o; o >>= 1) {
            a0 += __shfl_xor_sync(0xFFFFFFFFu, a0, o);
            a1 += __shfl_xor_sync(0xFFFFFFFFu, a1, o);
        }
        if (lane == 0) { zw0_s[wid] = a0; zw1_s[wid] = a1; }
    }

    // --- the single barrier, doubling as the sigma-uniformity vote ---
    const int nonuniform =
        __syncthreads_or((tid < ZDIM) && (__ldg(sigma + tid) != s0));

    float s_0, s_1;
    if (!nonuniform) {
        // two independent FMA chains per output
        float p0 = e[0] * zw0_s[0], q0 = e[1] * zw0_s[1];
        float p1 = e[0] * zw1_s[0], q1 = e[1] * zw1_s[1];
#pragma unroll
        for (int n = 2; n < CHUNK; n += 2) {
            p0 = fmaf(e[n],     zw0_s[n],     p0);
            q0 = fmaf(e[n + 1], zw0_s[n + 1], q0);
            p1 = fmaf(e[n],     zw1_s[n],     p1);
            q1 = fmaf(e[n + 1], zw1_s[n + 1], q1);
        }
        s_0 = p0 + q0;
        s_1 = p1 + q1;
    } else {
        // general path: per-channel length scales (correct for any sigma)
        s_0 = 0.f; s_1 = 0.f;
        for (int n = 0; n < CHUNK; ++n) {
            const float d  = xm - __ldg(tg + n);
            const float d2 = d * d;
            const float* zr = z + (size_t)(b * NN + n0 + n) * ZDIM;
            for (int c = 0; c < ZDIM; ++c) {
                const float inv = __expf(-__ldg(sigma + c));
                const float qq  = -0.5f * inv * inv;
                const float ev  = __ldg(zr + c) * __expf(qq * d2);
                s_0 = fmaf(ev, __ldg(W + c),        s_0);
                s_1 = fmaf(ev, __ldg(W + ZDIM + c), s_1);
            }
        }
    }

    // --- combine across the 64 chunk-blocks of this batch ---
    const int pt  = b * MM + m;                           // 0..2047
    float*    acc = g_acc + 2 * pt;
    red_add_v2(acc, s_0, s_1);
    const unsigned old = atom_inc_acqrel(&g_cnt[pt]);
    if (old == NCONTRIB - 1) {
        float a0, a1;
        ld_relaxed_v2(acc, a0, a1);
        out[2 * pt + 0] = a0 + b0;
        out[2 * pt + 1] = a1 + b1;
        st_relaxed_v2(acc, 0.0f, 0.0f);                   // reset for next replay
        st_relaxed_u32(&g_cnt[pt], 0u);
    }
}

// ---------------------------------------------------------------------------
extern "C" void kernel_launch(void* const* d_in, const int* in_sizes, int n_in,
                              void* d_out, int out_size) {
    const float* t     = (const float*)d_in[0];
    const float* z     = (const float*)d_in[1];
    const float* x     = (const float*)d_in[2];
    const float* sigma = (const float*)d_in[3];
    const float* W     = (const float*)d_in[4];
    const float* bias  = (const float*)d_in[5];
    float* out = (float*)d_out;

    decoder_v7<<<GRID, NTHREADS>>>(t, z, x, sigma, W, bias, out);
}